// round 15
// baseline (speedup 1.0000x reference)
#include <cuda_runtime.h>
#include <cuda_bf16.h>

typedef unsigned long long u64;
typedef unsigned int u32;

#define VOCAB   65
#define SQRT_C  5.656854249492381f   // faithful bug: scores MULTIPLIED by sqrt(32)

// ---------------- scratch (device globals; no allocations allowed) ----------
__device__ __align__(16) float g_Qtab[520 * 32];
__device__ __align__(16) float g_Ktab[520 * 32];   // pre-scaled by SQRT_C
__device__ __align__(16) float g_Vtab[520 * 32];
__device__ __align__(16) u32   g_bfrag[2304];      // Wlm bf16 hi/lo mma B-fragments (9 nt)
__device__ __align__(16) u32   g_mfrag[1024];      // Wmlp bf16 hi/lo mma B-fragments (4 nt)
__device__ float    g_loss;
__device__ unsigned g_done;

// ---------------- packed weights: one constant block, one memcpy ------------
#define WLM_STRIDE 68
#define OFF_WMLP   0           // [c][c2] 1024
#define OFF_BMLP   1024        // 32
#define OFF_BLM    1056        // 68 (65 + zero pad)
#define OFF_WLM    1124        // [c][v] 32*68 = 2176
#define PACK_N     3300
__device__   __align__(16) float g_pack[PACK_N];
__constant__ __align__(16) float c_all[PACK_N];

// ---------------- packed f32x2 helpers (sm_103a) ----------------------------
__device__ __forceinline__ u64 fma2(u64 a, u64 b, u64 c) {
    u64 d; asm("fma.rn.f32x2 %0, %1, %2, %3;" : "=l"(d) : "l"(a), "l"(b), "l"(c)); return d;
}
__device__ __forceinline__ u64 add2(u64 a, u64 b) {
    u64 d; asm("add.rn.f32x2 %0, %1, %2;" : "=l"(d) : "l"(a), "l"(b)); return d;
}
__device__ __forceinline__ float hadd2(u64 a) {
    float lo, hi; asm("mov.b64 {%0,%1}, %2;" : "=f"(lo), "=f"(hi) : "l"(a)); return lo + hi;
}
__device__ __forceinline__ u64 pack2(float lo, float hi) {
    u64 r; asm("mov.b64 %0, {%1,%2};" : "=l"(r) : "f"(lo), "f"(hi)); return r;
}
__device__ __forceinline__ float lo2(u64 a) {
    float lo, hi; asm("mov.b64 {%0,%1}, %2;" : "=f"(lo), "=f"(hi) : "l"(a)); return lo;
}
__device__ __forceinline__ float hi2(u64 a) {
    float lo, hi; asm("mov.b64 {%0,%1}, %2;" : "=f"(lo), "=f"(hi) : "l"(a)); return hi;
}
__device__ __forceinline__ ulonglong2 ldc4(const float* p) {
    return *reinterpret_cast<const ulonglong2*>(p);
}
__device__ __forceinline__ u64 ldc2(const float* p) {
    return *reinterpret_cast<const u64*>(p);
}
// m16n8k16 bf16 mma, f32 accumulate in-place
__device__ __forceinline__ void mma_bf16(float* d, const u32* a, u32 b0, u32 b1) {
    asm volatile("mma.sync.aligned.m16n8k16.row.col.f32.bf16.bf16.f32 "
                 "{%0,%1,%2,%3}, {%4,%5,%6,%7}, {%8,%9}, {%0,%1,%2,%3};"
                 : "+f"(d[0]), "+f"(d[1]), "+f"(d[2]), "+f"(d[3])
                 : "r"(a[0]), "r"(a[1]), "r"(a[2]), "r"(a[3]), "r"(b0), "r"(b1));
}

// Build one bf16 hi/lo B-fragment word for mma (row.col).
__device__ __forceinline__ u32 bfrag_word(float v0, float v1, int plane) {
    __nv_bfloat16 h0 = __float2bfloat16(v0), h1 = __float2bfloat16(v1);
    if (plane == 0)
        return (u32)__bfloat16_as_ushort(h0) | ((u32)__bfloat16_as_ushort(h1) << 16);
    __nv_bfloat16 l0 = __float2bfloat16(v0 - __bfloat162float(h0));
    __nv_bfloat16 l1 = __float2bfloat16(v1 - __bfloat162float(h1));
    return (u32)__bfloat16_as_ushort(l0) | ((u32)__bfloat16_as_ushort(l1) << 16);
}

// Precompute Q/K/V tables, pack weights, build Wlm + Wmlp mma B-fragments.
__global__ void k_tables(const float* __restrict__ tok_emb,
                         const float* __restrict__ pos_emb,
                         const float* __restrict__ Wq,
                         const float* __restrict__ Wk,
                         const float* __restrict__ Wv,
                         const float* __restrict__ Wmlp,
                         const float* __restrict__ bmlp,
                         const float* __restrict__ Wlm,
                         const float* __restrict__ blm) {
    int i = blockIdx.x * blockDim.x + threadIdx.x;
    if (i == 0) { g_loss = 0.0f; g_done = 0u; }
    if (i < 520 * 32) {
        int row = i >> 5, c = i & 31;
        int t = row / 65, tok = row % 65;
        int h = c >> 3, d = c & 7;
        float aq = 0.f, ak = 0.f, av = 0.f;
#pragma unroll
        for (int cc = 0; cc < 32; cc++) {
            float xv = tok_emb[tok * 32 + cc] + pos_emb[t * 32 + cc];
            int wi = h * 256 + cc * 8 + d;
            aq = fmaf(xv, Wq[wi], aq);
            ak = fmaf(xv, Wk[wi], ak);
            av = fmaf(xv, Wv[wi], av);
        }
        g_Qtab[i] = aq;
        g_Ktab[i] = ak * SQRT_C;
        g_Vtab[i] = av;
    } else if (i < 520 * 32 + PACK_N) {
        int i2 = i - 520 * 32;
        float v;
        if (i2 < OFF_BMLP)      v = Wmlp[i2];
        else if (i2 < OFF_BLM)  v = bmlp[i2 - OFF_BMLP];
        else if (i2 < OFF_WLM) {
            int j = i2 - OFF_BLM;
            v = (j < 65) ? blm[j] : 0.0f;
        } else {
            int j  = i2 - OFF_WLM;
            int c  = j / WLM_STRIDE;
            int vv = j - c * WLM_STRIDE;
            v = (vv < 65) ? Wlm[c * 65 + vv] : 0.0f;
        }
        g_pack[i2] = v;
    } else if (i < 520 * 32 + PACK_N + 2304) {
        // Wlm B-fragments: idx = ((nt*2 + plane)*32 + lane)*4 + kt*2 + reg
        int i3   = i - 520 * 32 - PACK_N;
        int reg  = i3 & 1;
        int kt   = (i3 >> 1) & 1;
        int lane = (i3 >> 2) & 31;
        int q    = i3 >> 7;
        int p    = q & 1;
        int nt   = q >> 1;
        int gid  = lane >> 2, tig = lane & 3;
        int n    = nt * 8 + gid;
        int k0   = tig * 2 + reg * 8 + kt * 16;
        float v0 = (n < 65) ? Wlm[k0 * 65 + n] : 0.f;
        float v1 = (n < 65) ? Wlm[(k0 + 1) * 65 + n] : 0.f;
        g_bfrag[i3] = bfrag_word(v0, v1, p);
    } else if (i < 520 * 32 + PACK_N + 2304 + 1024) {
        // Wmlp B-fragments (B[k=c][n=c2] = Wmlp[c*32+c2]); same layout, nt 0..3
        int i3   = i - 520 * 32 - PACK_N - 2304;
        int reg  = i3 & 1;
        int kt   = (i3 >> 1) & 1;
        int lane = (i3 >> 2) & 31;
        int q    = i3 >> 7;
        int p    = q & 1;
        int nt   = q >> 1;
        int gid  = lane >> 2, tig = lane & 3;
        int n    = nt * 8 + gid;
        int k0   = tig * 2 + reg * 8 + kt * 16;
        float v0 = Wmlp[k0 * 32 + n];
        float v1 = Wmlp[(k0 + 1) * 32 + n];
        g_mfrag[i3] = bfrag_word(v0, v1, p);
    }
}

#define KV_LS_STRIDE 264   // floats per sequence (K/V phase)
#define YB_ROW       144   // ovb row stride bytes (36 banks -> conflict-free A loads)

// 128 threads. Attention: thread = token. MLP + lm-head: HMMA.
__global__ __launch_bounds__(128, 4)
void k_main(const int* __restrict__ idx, const int* __restrict__ tgt,
            float* __restrict__ out, int write_logits,
            int loss_idx, float inv_n, int nblocks) {
    // s_un phases: K[0..4224) V[4224..8448) -> ovb bf16 -> stage [128][65]
    __shared__ __align__(16) float s_un[8448];
    __shared__ __align__(16) u32   s_bf[2304];    // Wlm fragments
    __shared__ __align__(16) u32   s_mf[1024];    // Wmlp fragments
    __shared__ __align__(16) float s_bias[72];
    __shared__ int                 s_tgt[128];
    __shared__ float               s_lred[4];

    const float* c_bmlp = c_all + OFF_BMLP;

    const int tid   = threadIdx.x;
    const int lane  = tid & 31;
    const int gid   = lane >> 2;
    const int tig   = lane & 3;
    const int wbase = (tid >> 5) * 32;
    const int ls    = tid >> 3;
    const int t     = tid & 7;
    const int rowg  = blockIdx.x * 128 + tid;
    const int tok   = idx[rowg];
    const int tgtv  = tgt[rowg];
    const int qrow  = (t * 65 + tok) * 32;

    s_tgt[tid] = tgtv;
    // stage fragments + bias
    {
        const uint4* src = reinterpret_cast<const uint4*>(g_bfrag);
        uint4*       dst = reinterpret_cast<uint4*>(s_bf);
        for (int i = tid; i < 576; i += 128) dst[i] = src[i];
        const uint4* src2 = reinterpret_cast<const uint4*>(g_mfrag);
        uint4*       dst2 = reinterpret_cast<uint4*>(s_mf);
        for (int i = tid; i < 256; i += 128) dst2[i] = src2[i];
    }
    if (tid < 72) s_bias[tid] = (tid < 65) ? g_pack[OFF_BLM + tid] : 0.f;

    // k, v rows into shared
    {
        const float4* k4 = reinterpret_cast<const float4*>(g_Ktab + qrow);
        const float4* v4 = reinterpret_cast<const float4*>(g_Vtab + qrow);
        float4* skd = reinterpret_cast<float4*>(s_un + ls * KV_LS_STRIDE + t * 32);
        float4* svd = reinterpret_cast<float4*>(s_un + 4224 + ls * KV_LS_STRIDE + t * 32);
#pragma unroll
        for (int j = 0; j < 8; j++) { skd[j] = k4[j]; svd[j] = v4[j]; }
    }
    __syncthreads();

    // ----- attention in head-pairs (proven structure) -----
    float ov[32];
#pragma unroll
    for (int hp = 0; hp < 2; hp++) {
        u64 q2[8];
        {
            const ulonglong2* q4 =
                reinterpret_cast<const ulonglong2*>(g_Qtab + qrow + hp * 16);
#pragma unroll
            for (int j = 0; j < 4; j++) {
                ulonglong2 a = q4[j];
                q2[2 * j] = a.x; q2[2 * j + 1] = a.y;
            }
        }
        float sc[2][8];
        const float* kb = s_un + ls * KV_LS_STRIDE + hp * 16;
#pragma unroll
        for (int s = 0; s < 8; s++) {
            const ulonglong2* kr = reinterpret_cast<const ulonglong2*>(kb + s * 32);
            ulonglong2 a = kr[0], b = kr[1], c = kr[2], d = kr[3];
            u64 e0 = 0ull, e1 = 0ull, f0 = 0ull, f1 = 0ull;
            e0 = fma2(q2[0], a.x, e0); e1 = fma2(q2[1], a.y, e1);
            e0 = fma2(q2[2], b.x, e0); e1 = fma2(q2[3], b.y, e1);
            f0 = fma2(q2[4], c.x, f0); f1 = fma2(q2[5], c.y, f1);
            f0 = fma2(q2[6], d.x, f0); f1 = fma2(q2[7], d.y, f1);
            float se = hadd2(add2(e0, e1));
            float sf = hadd2(add2(f0, f1));
            sc[0][s] = (s <= t) ? se : -1e30f;
            sc[1][s] = (s <= t) ? sf : -1e30f;
        }
        float rinv[2];
#pragma unroll
        for (int hh = 0; hh < 2; hh++) {
            float m01 = fmaxf(sc[hh][0], sc[hh][1]);
            float m23 = fmaxf(sc[hh][2], sc[hh][3]);
            float m45 = fmaxf(sc[hh][4], sc[hh][5]);
            float m67 = fmaxf(sc[hh][6], sc[hh][7]);
            float m = fmaxf(fmaxf(m01, m23), fmaxf(m45, m67));
            float sum = 0.f;
#pragma unroll
            for (int s = 0; s < 8; s++) {
                float e = __expf(sc[hh][s] - m);
                sc[hh][s] = e;
                sum += e;
            }
            rinv[hh] = __fdividef(1.0f, sum);
        }
        u64 oacc[8];
#pragma unroll
        for (int j = 0; j < 8; j++) oacc[j] = 0ull;
        const float* vb = s_un + 4224 + ls * KV_LS_STRIDE + hp * 16;
#pragma unroll
        for (int s = 0; s < 8; s++) {
            const ulonglong2* vr = reinterpret_cast<const ulonglong2*>(vb + s * 32);
            ulonglong2 a = vr[0], b = vr[1], c = vr[2], d = vr[3];
            float p0 = sc[0][s] * rinv[0];
            float p1 = sc[1][s] * rinv[1];
            u64 p02 = pack2(p0, p0), p12 = pack2(p1, p1);
            oacc[0] = fma2(p02, a.x, oacc[0]); oacc[1] = fma2(p02, a.y, oacc[1]);
            oacc[2] = fma2(p02, b.x, oacc[2]); oacc[3] = fma2(p02, b.y, oacc[3]);
            oacc[4] = fma2(p12, c.x, oacc[4]); oacc[5] = fma2(p12, c.y, oacc[5]);
            oacc[6] = fma2(p12, d.x, oacc[6]); oacc[7] = fma2(p12, d.y, oacc[7]);
        }
#pragma unroll
        for (int j = 0; j < 8; j++) {
            ov[hp * 16 + 2 * j]     = lo2(oacc[j]);
            ov[hp * 16 + 2 * j + 1] = hi2(oacc[j]);
        }
    }
    __syncthreads();   // all K/V reads done -> s_un reusable

    // ----- ov -> bf16 hi/lo planes in smem (A operand of MLP mma) -----
    char* ybb = reinterpret_cast<char*>(s_un);
#pragma unroll
    for (int j = 0; j < 16; j++) {
        float y0 = ov[2 * j], y1 = ov[2 * j + 1];
        u32 hp;
        asm("cvt.rn.bf16x2.f32 %0, %1, %2;" : "=r"(hp) : "f"(y1), "f"(y0));
        float l0 = y0 - __uint_as_float(hp << 16);
        float l1 = y1 - __uint_as_float(hp & 0xffff0000u);
        u32 lp;
        asm("cvt.rn.bf16x2.f32 %0, %1, %2;" : "=r"(lp) : "f"(l1), "f"(l0));
        *reinterpret_cast<u32*>(ybb + tid * YB_ROW + j * 4)      = hp;
        *reinterpret_cast<u32*>(ybb + tid * YB_ROW + 64 + j * 4) = lp;
    }
    __syncthreads();

    // ----- load ov A fragments -----
    u32 af[2][2][2][4];
#pragma unroll
    for (int mt = 0; mt < 2; mt++)
#pragma unroll
        for (int p = 0; p < 2; p++)
#pragma unroll
            for (int kt = 0; kt < 2; kt++) {
                int r0   = (wbase + mt * 16 + gid) * YB_ROW;
                int colb = p * 64 + kt * 32 + tig * 4;
                af[mt][p][kt][0] = *reinterpret_cast<const u32*>(ybb + r0 + colb);
                af[mt][p][kt][1] = *reinterpret_cast<const u32*>(ybb + r0 + 8 * YB_ROW + colb);
                af[mt][p][kt][2] = *reinterpret_cast<const u32*>(ybb + r0 + colb + 16);
                af[mt][p][kt][3] = *reinterpret_cast<const u32*>(ybb + r0 + 8 * YB_ROW + colb + 16);
            }
    __syncthreads();   // A frags in regs -> stage region writable

    // ----- MLP via mma: D[128x32] = ov @ Wmlp, bias+relu in regs -----
    float dm[2][4][4];
#pragma unroll
    for (int nn = 0; nn < 4; nn++) {
        u64 bp = ldc2(c_bmlp + nn * 8 + tig * 2);
        float b0 = lo2(bp), b1 = hi2(bp);
#pragma unroll
        for (int mt = 0; mt < 2; mt++) {
            dm[mt][nn][0] = b0; dm[mt][nn][1] = b1;
            dm[mt][nn][2] = b0; dm[mt][nn][3] = b1;
        }
    }
#pragma unroll
    for (int nn = 0; nn < 4; nn++) {
        uint4 bh = *reinterpret_cast<const uint4*>(s_mf + (nn * 2 + 0) * 128 + lane * 4);
        uint4 bl = *reinterpret_cast<const uint4*>(s_mf + (nn * 2 + 1) * 128 + lane * 4);
#pragma unroll
        for (int mt = 0; mt < 2; mt++) {
            mma_bf16(dm[mt][nn], af[mt][0][0], bh.x, bh.y);
            mma_bf16(dm[mt][nn], af[mt][0][1], bh.z, bh.w);
            mma_bf16(dm[mt][nn], af[mt][1][0], bh.x, bh.y);
            mma_bf16(dm[mt][nn], af[mt][1][1], bh.z, bh.w);
            mma_bf16(dm[mt][nn], af[mt][0][0], bl.x, bl.y);
            mma_bf16(dm[mt][nn], af[mt][0][1], bl.z, bl.w);
        }
    }

    // ----- relu + register transform: MLP D -> lm-head A fragments -----
    u32 yf[2][2][2][4];   // [mt][plane][kt][reg]
#pragma unroll
    for (int mt = 0; mt < 2; mt++)
#pragma unroll
        for (int kt = 0; kt < 2; kt++)
#pragma unroll
            for (int r = 0; r < 4; r++) {
                int nn   = kt * 2 + (r >> 1);
                int base = (r & 1) * 2;
                float y0 = fmaxf(dm[mt][nn][base],     0.f);
                float y1 = fmaxf(dm[mt][nn][base + 1], 0.f);
                u32 hp;
                asm("cvt.rn.bf16x2.f32 %0, %1, %2;" : "=r"(hp) : "f"(y1), "f"(y0));
                float l0 = y0 - __uint_as_float(hp << 16);
                float l1 = y1 - __uint_as_float(hp & 0xffff0000u);
                u32 lp;
                asm("cvt.rn.bf16x2.f32 %0, %1, %2;" : "=r"(lp) : "f"(l1), "f"(l0));
                yf[mt][0][kt][r] = hp;
                yf[mt][1][kt][r] = lp;
            }

    // ----- lm-head mma passes + in-register online LSE -----
    float m_r[4] = {-1e30f, -1e30f, -1e30f, -1e30f};
    float s_r[4] = {0.f, 0.f, 0.f, 0.f};
    float acc[2][5][4];

#define MMA_PASS(NTS, CNT)                                                     \
    {                                                                          \
        _Pragma("unroll")                                                      \
        for (int nn = 0; nn < (CNT); nn++) {                                   \
            int v0 = ((NTS) + nn) * 8 + tig * 2;                               \
            float b0 = s_bias[v0], b1 = s_bias[v0 + 1];                        \
            _Pragma("unroll")                                                  \
            for (int mt = 0; mt < 2; mt++) {                                   \
                acc[mt][nn][0] = b0; acc[mt][nn][1] = b1;                      \
                acc[mt][nn][2] = b0; acc[mt][nn][3] = b1;                      \
            }                                                                  \
        }                                                                      \
        _Pragma("unroll")                                                      \
        for (int nn = 0; nn < (CNT); nn++) {                                   \
            int nt = (NTS) + nn;                                               \
            uint4 bh = *reinterpret_cast<const uint4*>(s_bf + (nt * 2 + 0) * 128 + lane * 4); \
            uint4 bl = *reinterpret_cast<const uint4*>(s_bf + (nt * 2 + 1) * 128 + lane * 4); \
            _Pragma("unroll")                                                  \
            for (int mt = 0; mt < 2; mt++) {                                   \
                mma_bf16(acc[mt][nn], yf[mt][0][0], bh.x, bh.y);               \
                mma_bf16(acc[mt][nn], yf[mt][0][1], bh.z, bh.w);               \
                mma_bf16(acc[mt][nn], yf[mt][1][0], bh.x, bh.y);               \
                mma_bf16(acc[mt][nn], yf[mt][1][1], bh.z, bh.w);               \
                mma_bf16(acc[mt][nn], yf[mt][0][0], bl.x, bl.y);               \
                mma_bf16(acc[mt][nn], yf[mt][0][1], bl.z, bl.w);               \
            }                                                                  \
        }                                                                      \
        _Pragma("unroll")                                                      \
        for (int nn = 0; nn < (CNT); nn++) {                                   \
            int v0 = ((NTS) + nn) * 8 + tig * 2;                               \
            _Pragma("unroll")                                                  \
            for (int mt = 0; mt < 2; mt++) {                                   \
                int r0 = wbase + mt * 16 + gid;                                \
                if (v0 < 65) {                                                 \
                    s_un[r0 * 65 + v0]       = acc[mt][nn][0];                 \
                    s_un[(r0 + 8) * 65 + v0] = acc[mt][nn][2];                 \
                }                                                              \
                if (v0 + 1 < 65) {                                             \
                    s_un[r0 * 65 + v0 + 1]       = acc[mt][nn][1];             \
                    s_un[(r0 + 8) * 65 + v0 + 1] = acc[mt][nn][3];             \
                }                                                              \
            }                                                                  \
        }                                                                      \
        _Pragma("unroll")                                                      \
        for (int q = 0; q < 4; q++) {                                          \
            int mt = q >> 1, hh = (q & 1) * 2;                                 \
            float l[2 * (CNT)];                                                \
            float cm = -1e30f;                                                 \
            _Pragma("unroll")                                                  \
            for (int nn = 0; nn < (CNT); nn++) {                               \
                int v0 = ((NTS) + nn) * 8 + tig * 2;                           \
                l[2 * nn]     = (v0 < 65)     ? acc[mt][nn][hh]     : -1e30f;  \
                l[2 * nn + 1] = (v0 + 1 < 65) ? acc[mt][nn][hh + 1] : -1e30f;  \
                cm = fmaxf(cm, fmaxf(l[2 * nn], l[2 * nn + 1]));               \
            }                                                                  \
            float mn = fmaxf(m_r[q], cm);                                      \
            float s2 = s_r[q] * __expf(m_r[q] - mn);                           \
            _Pragma("unroll")                                                  \
            for (int j = 0; j < 2 * (CNT); j++) s2 += __expf(l[j] - mn);       \
            m_r[q] = mn; s_r[q] = s2;                                          \
        }                                                                      \
    }
    MMA_PASS(0, 5)
    MMA_PASS(5, 4)
#undef MMA_PASS

    // ----- combine LSE partials across the 4 tig lanes (bfly) -----
#pragma unroll
    for (int mask = 1; mask <= 2; mask <<= 1) {
#pragma unroll
        for (int q = 0; q < 4; q++) {
            float mo = __shfl_xor_sync(0xffffffffu, m_r[q], mask);
            float so = __shfl_xor_sync(0xffffffffu, s_r[q], mask);
            float mn = fmaxf(m_r[q], mo);
            s_r[q] = s_r[q] * __expf(m_r[q] - mn) + so * __expf(mo - mn);
            m_r[q] = mn;
        }
    }
    __syncthreads();   // stage complete for ltgt reads + flush

    // lane reports row = wbase + tig*8 + gid  (q = tig)
    float msel = m_r[0], ssel = s_r[0];
    if (tig == 1) { msel = m_r[1]; ssel = s_r[1]; }
    else if (tig == 2) { msel = m_r[2]; ssel = s_r[2]; }
    else if (tig == 3) { msel = m_r[3]; ssel = s_r[3]; }
    int trow = wbase + tig * 8 + gid;
    float ltgt = s_un[trow * 65 + s_tgt[trow]];
    float lossi = (msel + __logf(ssel)) - ltgt;

    // warp then block reduce; last block writes mean
#pragma unroll
    for (int off = 16; off > 0; off >>= 1)
        lossi += __shfl_down_sync(0xffffffffu, lossi, off);
    if ((tid & 31) == 0) s_lred[tid >> 5] = lossi;
    __syncthreads();
    if (tid == 0) {
        atomicAdd(&g_loss, s_lred[0] + s_lred[1] + s_lred[2] + s_lred[3]);
        __threadfence();
        unsigned prev = atomicAdd(&g_done, 1u);
        if ((int)prev == nblocks - 1 && loss_idx >= 0)
            out[loss_idx] = g_loss * inv_n;
    }

    // ----- single TMA bulk store: stage -> GMEM logits -----
    if (write_logits && tid == 0) {
        u32 saddr;
        asm("{ .reg .u64 tmp; cvta.to.shared.u64 tmp, %1; cvt.u32.u64 %0, tmp; }"
            : "=r"(saddr) : "l"(s_un));
        const float* gdst = out + (size_t)blockIdx.x * 8320;
        asm volatile("fence.proxy.async.shared::cta;" ::: "memory");
        asm volatile("cp.async.bulk.global.shared::cta.bulk_group [%0], [%1], %2;"
                     :: "l"(gdst), "r"(saddr), "r"(33280) : "memory");
        asm volatile("cp.async.bulk.commit_group;" ::: "memory");
        asm volatile("cp.async.bulk.wait_group.read 0;" ::: "memory");
    }
}

extern "C" void kernel_launch(void* const* d_in, const int* in_sizes, int n_in,
                              void* d_out, int out_size) {
    const int*   idx     = (const int*)d_in[0];
    const int*   targets = (const int*)d_in[1];
    const float* tok_emb = (const float*)d_in[2];
    const float* pos_emb = (const float*)d_in[3];
    const float* Wq      = (const float*)d_in[4];
    const float* Wk      = (const float*)d_in[5];
    const float* Wv      = (const float*)d_in[6];
    const float* Wmlp    = (const float*)d_in[7];
    const float* bmlp    = (const float*)d_in[8];
    const float* Wlm     = (const float*)d_in[9];
    const float* blm     = (const float*)d_in[10];
    float* out = (float*)d_out;

    const long nrows = in_sizes[0];           // B*T = 524288
    const long total = nrows * VOCAB;
    int write_logits = ((long)out_size >= total) ? 1 : 0;
    int loss_idx = -1;
    if ((long)out_size == total + 1) loss_idx = (int)total;
    else if (out_size == 1)          { loss_idx = 0; write_logits = 0; }

    int work = 520 * 32 + PACK_N + 2304 + 1024;
    k_tables<<<(work + 255) / 256, 256>>>(tok_emb, pos_emb, Wq, Wk, Wv,
                                          Wmlp, bmlp, Wlm, blm);
    {
        void* src = nullptr;
        cudaGetSymbolAddress(&src, g_pack);
        cudaMemcpyToSymbolAsync(c_all, src, PACK_N * sizeof(float), 0,
                                cudaMemcpyDeviceToDevice);
    }

    int nblocks = (int)(nrows / 128);
    k_main<<<nblocks, 128>>>(idx, targets, out, write_logits, loss_idx,
                             1.0f / (float)nrows, nblocks);
}

// round 16
// speedup vs baseline: 1.3593x; 1.3593x over previous
#include <cuda_runtime.h>
#include <cuda_bf16.h>

typedef unsigned long long u64;
typedef unsigned int u32;

#define VOCAB   65
#define SQRT_C  5.656854249492381f   // faithful bug: scores MULTIPLIED by sqrt(32)

// ---------------- scratch (device globals; no allocations allowed) ----------
__device__ __align__(16) float g_Qtab[520 * 32];
__device__ __align__(16) float g_Ktab[520 * 32];   // pre-scaled by SQRT_C
__device__ __align__(16) float g_Vtab[520 * 32];
__device__ __align__(16) u32   g_bfrag[2304];      // Wlm bf16 hi/lo mma B-fragments (9 nt)
__device__ __align__(16) u32   g_mfrag[1024];      // Wmlp bf16 hi/lo mma B-fragments (4 nt)
__device__ float    g_loss;
__device__ unsigned g_done;

// ---------------- packed weights: one constant block, one memcpy ------------
#define WLM_STRIDE 68
#define OFF_WMLP   0           // [c][c2] 1024
#define OFF_BMLP   1024        // 32
#define OFF_BLM    1056        // 68 (65 + zero pad)
#define OFF_WLM    1124        // [c][v] 32*68 = 2176
#define PACK_N     3300
__device__   __align__(16) float g_pack[PACK_N];
__constant__ __align__(16) float c_all[PACK_N];

// ---------------- packed f32x2 helpers (sm_103a) ----------------------------
__device__ __forceinline__ u64 fma2(u64 a, u64 b, u64 c) {
    u64 d; asm("fma.rn.f32x2 %0, %1, %2, %3;" : "=l"(d) : "l"(a), "l"(b), "l"(c)); return d;
}
__device__ __forceinline__ u64 add2(u64 a, u64 b) {
    u64 d; asm("add.rn.f32x2 %0, %1, %2;" : "=l"(d) : "l"(a), "l"(b)); return d;
}
__device__ __forceinline__ float hadd2(u64 a) {
    float lo, hi; asm("mov.b64 {%0,%1}, %2;" : "=f"(lo), "=f"(hi) : "l"(a)); return lo + hi;
}
__device__ __forceinline__ u64 pack2(float lo, float hi) {
    u64 r; asm("mov.b64 %0, {%1,%2};" : "=l"(r) : "f"(lo), "f"(hi)); return r;
}
__device__ __forceinline__ float lo2(u64 a) {
    float lo, hi; asm("mov.b64 {%0,%1}, %2;" : "=f"(lo), "=f"(hi) : "l"(a)); return lo;
}
__device__ __forceinline__ float hi2(u64 a) {
    float lo, hi; asm("mov.b64 {%0,%1}, %2;" : "=f"(lo), "=f"(hi) : "l"(a)); return hi;
}
__device__ __forceinline__ u64 ldc2(const float* p) {
    return *reinterpret_cast<const u64*>(p);
}
// m16n8k16 bf16 mma, f32 accumulate in-place
__device__ __forceinline__ void mma_bf16(float* d, const u32* a, u32 b0, u32 b1) {
    asm volatile("mma.sync.aligned.m16n8k16.row.col.f32.bf16.bf16.f32 "
                 "{%0,%1,%2,%3}, {%4,%5,%6,%7}, {%8,%9}, {%0,%1,%2,%3};"
                 : "+f"(d[0]), "+f"(d[1]), "+f"(d[2]), "+f"(d[3])
                 : "r"(a[0]), "r"(a[1]), "r"(a[2]), "r"(a[3]), "r"(b0), "r"(b1));
}

// Build one bf16 hi/lo B-fragment word for mma (row.col).
__device__ __forceinline__ u32 bfrag_word(float v0, float v1, int plane) {
    __nv_bfloat16 h0 = __float2bfloat16(v0), h1 = __float2bfloat16(v1);
    if (plane == 0)
        return (u32)__bfloat16_as_ushort(h0) | ((u32)__bfloat16_as_ushort(h1) << 16);
    __nv_bfloat16 l0 = __float2bfloat16(v0 - __bfloat162float(h0));
    __nv_bfloat16 l1 = __float2bfloat16(v1 - __bfloat162float(h1));
    return (u32)__bfloat16_as_ushort(l0) | ((u32)__bfloat16_as_ushort(l1) << 16);
}

// Precompute Q/K/V tables, pack weights, build Wlm + Wmlp mma B-fragments.
__global__ void k_tables(const float* __restrict__ tok_emb,
                         const float* __restrict__ pos_emb,
                         const float* __restrict__ Wq,
                         const float* __restrict__ Wk,
                         const float* __restrict__ Wv,
                         const float* __restrict__ Wmlp,
                         const float* __restrict__ bmlp,
                         const float* __restrict__ Wlm,
                         const float* __restrict__ blm) {
    int i = blockIdx.x * blockDim.x + threadIdx.x;
    if (i == 0) { g_loss = 0.0f; g_done = 0u; }
    if (i < 520 * 32) {
        int row = i >> 5, c = i & 31;
        int t = row / 65, tok = row % 65;
        int h = c >> 3, d = c & 7;
        float aq = 0.f, ak = 0.f, av = 0.f;
#pragma unroll
        for (int cc = 0; cc < 32; cc++) {
            float xv = tok_emb[tok * 32 + cc] + pos_emb[t * 32 + cc];
            int wi = h * 256 + cc * 8 + d;
            aq = fmaf(xv, Wq[wi], aq);
            ak = fmaf(xv, Wk[wi], ak);
            av = fmaf(xv, Wv[wi], av);
        }
        g_Qtab[i] = aq;
        g_Ktab[i] = ak * SQRT_C;
        g_Vtab[i] = av;
    } else if (i < 520 * 32 + PACK_N) {
        int i2 = i - 520 * 32;
        float v;
        if (i2 < OFF_BMLP)      v = Wmlp[i2];
        else if (i2 < OFF_BLM)  v = bmlp[i2 - OFF_BMLP];
        else if (i2 < OFF_WLM) {
            int j = i2 - OFF_BLM;
            v = (j < 65) ? blm[j] : 0.0f;
        } else {
            int j  = i2 - OFF_WLM;
            int c  = j / WLM_STRIDE;
            int vv = j - c * WLM_STRIDE;
            v = (vv < 65) ? Wlm[c * 65 + vv] : 0.0f;
        }
        g_pack[i2] = v;
    } else if (i < 520 * 32 + PACK_N + 2304) {
        // Wlm B-fragments: idx = ((nt*2 + plane)*32 + lane)*4 + kt*2 + reg
        int i3   = i - 520 * 32 - PACK_N;
        int reg  = i3 & 1;
        int kt   = (i3 >> 1) & 1;
        int lane = (i3 >> 2) & 31;
        int q    = i3 >> 7;
        int p    = q & 1;
        int nt   = q >> 1;
        int gid  = lane >> 2, tig = lane & 3;
        int n    = nt * 8 + gid;
        int k0   = tig * 2 + reg * 8 + kt * 16;
        float v0 = (n < 65) ? Wlm[k0 * 65 + n] : 0.f;
        float v1 = (n < 65) ? Wlm[(k0 + 1) * 65 + n] : 0.f;
        g_bfrag[i3] = bfrag_word(v0, v1, p);
    } else if (i < 520 * 32 + PACK_N + 2304 + 1024) {
        // Wmlp B-fragments (B[k=c][n=c2] = Wmlp[c*32+c2]); same layout, nt 0..3
        int i3   = i - 520 * 32 - PACK_N - 2304;
        int reg  = i3 & 1;
        int kt   = (i3 >> 1) & 1;
        int lane = (i3 >> 2) & 31;
        int q    = i3 >> 7;
        int p    = q & 1;
        int nt   = q >> 1;
        int gid  = lane >> 2, tig = lane & 3;
        int n    = nt * 8 + gid;
        int k0   = tig * 2 + reg * 8 + kt * 16;
        float v0 = Wmlp[k0 * 32 + n];
        float v1 = Wmlp[(k0 + 1) * 32 + n];
        g_mfrag[i3] = bfrag_word(v0, v1, p);
    }
}

#define KV_LS_STRIDE 264   // floats per sequence (K/V phase)
#define YB_ROW       144   // ovb row stride bytes (36 banks -> conflict-free A loads)

// 128 threads. Attention: thread = token. MLP + lm-head: HMMA.
// K/V staging is warp-cooperative: 4 table rows per warp instruction.
__global__ __launch_bounds__(128, 4)
void k_main(const int* __restrict__ idx, const int* __restrict__ tgt,
            float* __restrict__ out, int write_logits,
            int loss_idx, float inv_n, int nblocks) {
    // s_un phases: K[0..4224) V[4224..8448) -> ovb bf16 -> stage [128][65]
    __shared__ __align__(16) float s_un[8448];
    __shared__ __align__(16) u32   s_bf[2304];    // Wlm fragments
    __shared__ __align__(16) u32   s_mf[1024];    // Wmlp fragments
    __shared__ __align__(16) float s_bias[72];
    __shared__ int                 s_tgt[128];
    __shared__ int                 s_qrow[128];
    __shared__ float               s_lred[4];

    const float* c_bmlp = c_all + OFF_BMLP;

    const int tid   = threadIdx.x;
    const int lane  = tid & 31;
    const int gid   = lane >> 2;
    const int tig   = lane & 3;
    const int wbase = (tid >> 5) * 32;
    const int ls    = tid >> 3;
    const int t     = tid & 7;
    const int rowg  = blockIdx.x * 128 + tid;
    const int tok   = idx[rowg];
    const int tgtv  = tgt[rowg];
    const int qrow  = (t * 65 + tok) * 32;

    s_tgt[tid]  = tgtv;
    s_qrow[tid] = qrow;
    // stage fragments + bias
    {
        const uint4* src = reinterpret_cast<const uint4*>(g_bfrag);
        uint4*       dst = reinterpret_cast<uint4*>(s_bf);
        for (int i = tid; i < 576; i += 128) dst[i] = src[i];
        const uint4* src2 = reinterpret_cast<const uint4*>(g_mfrag);
        uint4*       dst2 = reinterpret_cast<uint4*>(s_mf);
        for (int i = tid; i < 256; i += 128) dst2[i] = src2[i];
    }
    if (tid < 72) s_bias[tid] = (tid < 65) ? g_pack[OFF_BLM + tid] : 0.f;
    __syncthreads();   // s_qrow visible

    // ----- cooperative K/V staging: 8 lanes per row, 4 rows per instr -----
    {
        const int w  = tid >> 5;
        const int g  = (tid >> 3) & 3;   // sub-group = sequence within warp
        const int wd = tid & 7;          // 16B word within row
        const int lsr = w * 4 + g;       // destination sequence
#pragma unroll
        for (int j = 0; j < 8; j++) {
            int r  = w * 32 + g * 8 + j;             // token row handled
            int qr = s_qrow[r];
            float4 kv = *reinterpret_cast<const float4*>(g_Ktab + qr + wd * 4);
            float4 vv = *reinterpret_cast<const float4*>(g_Vtab + qr + wd * 4);
            *reinterpret_cast<float4*>(s_un + lsr * KV_LS_STRIDE + j * 32 + wd * 4) = kv;
            *reinterpret_cast<float4*>(s_un + 4224 + lsr * KV_LS_STRIDE + j * 32 + wd * 4) = vv;
        }
    }
    __syncthreads();

    // ----- attention in head-pairs (proven structure) -----
    float ov[32];
#pragma unroll
    for (int hp = 0; hp < 2; hp++) {
        u64 q2[8];
        {
            const ulonglong2* q4 =
                reinterpret_cast<const ulonglong2*>(g_Qtab + qrow + hp * 16);
#pragma unroll
            for (int j = 0; j < 4; j++) {
                ulonglong2 a = q4[j];
                q2[2 * j] = a.x; q2[2 * j + 1] = a.y;
            }
        }
        float sc[2][8];
        const float* kb = s_un + ls * KV_LS_STRIDE + hp * 16;
#pragma unroll
        for (int s = 0; s < 8; s++) {
            const ulonglong2* kr = reinterpret_cast<const ulonglong2*>(kb + s * 32);
            ulonglong2 a = kr[0], b = kr[1], c = kr[2], d = kr[3];
            u64 e0 = 0ull, e1 = 0ull, f0 = 0ull, f1 = 0ull;
            e0 = fma2(q2[0], a.x, e0); e1 = fma2(q2[1], a.y, e1);
            e0 = fma2(q2[2], b.x, e0); e1 = fma2(q2[3], b.y, e1);
            f0 = fma2(q2[4], c.x, f0); f1 = fma2(q2[5], c.y, f1);
            f0 = fma2(q2[6], d.x, f0); f1 = fma2(q2[7], d.y, f1);
            float se = hadd2(add2(e0, e1));
            float sf = hadd2(add2(f0, f1));
            sc[0][s] = (s <= t) ? se : -1e30f;
            sc[1][s] = (s <= t) ? sf : -1e30f;
        }
        float rinv[2];
#pragma unroll
        for (int hh = 0; hh < 2; hh++) {
            float m01 = fmaxf(sc[hh][0], sc[hh][1]);
            float m23 = fmaxf(sc[hh][2], sc[hh][3]);
            float m45 = fmaxf(sc[hh][4], sc[hh][5]);
            float m67 = fmaxf(sc[hh][6], sc[hh][7]);
            float m = fmaxf(fmaxf(m01, m23), fmaxf(m45, m67));
            float sum = 0.f;
#pragma unroll
            for (int s = 0; s < 8; s++) {
                float e = __expf(sc[hh][s] - m);
                sc[hh][s] = e;
                sum += e;
            }
            rinv[hh] = __fdividef(1.0f, sum);
        }
        u64 oacc[8];
#pragma unroll
        for (int j = 0; j < 8; j++) oacc[j] = 0ull;
        const float* vb = s_un + 4224 + ls * KV_LS_STRIDE + hp * 16;
#pragma unroll
        for (int s = 0; s < 8; s++) {
            const ulonglong2* vr = reinterpret_cast<const ulonglong2*>(vb + s * 32);
            ulonglong2 a = vr[0], b = vr[1], c = vr[2], d = vr[3];
            float p0 = sc[0][s] * rinv[0];
            float p1 = sc[1][s] * rinv[1];
            u64 p02 = pack2(p0, p0), p12 = pack2(p1, p1);
            oacc[0] = fma2(p02, a.x, oacc[0]); oacc[1] = fma2(p02, a.y, oacc[1]);
            oacc[2] = fma2(p02, b.x, oacc[2]); oacc[3] = fma2(p02, b.y, oacc[3]);
            oacc[4] = fma2(p12, c.x, oacc[4]); oacc[5] = fma2(p12, c.y, oacc[5]);
            oacc[6] = fma2(p12, d.x, oacc[6]); oacc[7] = fma2(p12, d.y, oacc[7]);
        }
#pragma unroll
        for (int j = 0; j < 8; j++) {
            ov[hp * 16 + 2 * j]     = lo2(oacc[j]);
            ov[hp * 16 + 2 * j + 1] = hi2(oacc[j]);
        }
    }
    __syncthreads();   // all K/V reads done -> s_un reusable

    // ----- ov -> bf16 hi/lo planes in smem (A operand of MLP mma) -----
    char* ybb = reinterpret_cast<char*>(s_un);
#pragma unroll
    for (int j = 0; j < 16; j++) {
        float y0 = ov[2 * j], y1 = ov[2 * j + 1];
        u32 hp;
        asm("cvt.rn.bf16x2.f32 %0, %1, %2;" : "=r"(hp) : "f"(y1), "f"(y0));
        float l0 = y0 - __uint_as_float(hp << 16);
        float l1 = y1 - __uint_as_float(hp & 0xffff0000u);
        u32 lp;
        asm("cvt.rn.bf16x2.f32 %0, %1, %2;" : "=r"(lp) : "f"(l1), "f"(l0));
        *reinterpret_cast<u32*>(ybb + tid * YB_ROW + j * 4)      = hp;
        *reinterpret_cast<u32*>(ybb + tid * YB_ROW + 64 + j * 4) = lp;
    }
    __syncthreads();

    // ----- load ov A fragments -----
    u32 af[2][2][2][4];
#pragma unroll
    for (int mt = 0; mt < 2; mt++)
#pragma unroll
        for (int p = 0; p < 2; p++)
#pragma unroll
            for (int kt = 0; kt < 2; kt++) {
                int r0   = (wbase + mt * 16 + gid) * YB_ROW;
                int colb = p * 64 + kt * 32 + tig * 4;
                af[mt][p][kt][0] = *reinterpret_cast<const u32*>(ybb + r0 + colb);
                af[mt][p][kt][1] = *reinterpret_cast<const u32*>(ybb + r0 + 8 * YB_ROW + colb);
                af[mt][p][kt][2] = *reinterpret_cast<const u32*>(ybb + r0 + colb + 16);
                af[mt][p][kt][3] = *reinterpret_cast<const u32*>(ybb + r0 + 8 * YB_ROW + colb + 16);
            }
    __syncthreads();   // A frags in regs -> stage region writable

    // ----- MLP via mma: D[128x32] = ov @ Wmlp, bias+relu in regs -----
    float dm[2][4][4];
#pragma unroll
    for (int nn = 0; nn < 4; nn++) {
        u64 bp = ldc2(c_bmlp + nn * 8 + tig * 2);
        float b0 = lo2(bp), b1 = hi2(bp);
#pragma unroll
        for (int mt = 0; mt < 2; mt++) {
            dm[mt][nn][0] = b0; dm[mt][nn][1] = b1;
            dm[mt][nn][2] = b0; dm[mt][nn][3] = b1;
        }
    }
#pragma unroll
    for (int nn = 0; nn < 4; nn++) {
        uint4 bh = *reinterpret_cast<const uint4*>(s_mf + (nn * 2 + 0) * 128 + lane * 4);
        uint4 bl = *reinterpret_cast<const uint4*>(s_mf + (nn * 2 + 1) * 128 + lane * 4);
#pragma unroll
        for (int mt = 0; mt < 2; mt++) {
            mma_bf16(dm[mt][nn], af[mt][0][0], bh.x, bh.y);
            mma_bf16(dm[mt][nn], af[mt][0][1], bh.z, bh.w);
            mma_bf16(dm[mt][nn], af[mt][1][0], bh.x, bh.y);
            mma_bf16(dm[mt][nn], af[mt][1][1], bh.z, bh.w);
            mma_bf16(dm[mt][nn], af[mt][0][0], bl.x, bl.y);
            mma_bf16(dm[mt][nn], af[mt][0][1], bl.z, bl.w);
        }
    }

    // ----- relu + register transform: MLP D -> lm-head A fragments -----
    u32 yf[2][2][2][4];   // [mt][plane][kt][reg]
#pragma unroll
    for (int mt = 0; mt < 2; mt++)
#pragma unroll
        for (int kt = 0; kt < 2; kt++)
#pragma unroll
            for (int r = 0; r < 4; r++) {
                int nn   = kt * 2 + (r >> 1);
                int base = (r & 1) * 2;
                float y0 = fmaxf(dm[mt][nn][base],     0.f);
                float y1 = fmaxf(dm[mt][nn][base + 1], 0.f);
                u32 hp;
                asm("cvt.rn.bf16x2.f32 %0, %1, %2;" : "=r"(hp) : "f"(y1), "f"(y0));
                float l0 = y0 - __uint_as_float(hp << 16);
                float l1 = y1 - __uint_as_float(hp & 0xffff0000u);
                u32 lp;
                asm("cvt.rn.bf16x2.f32 %0, %1, %2;" : "=r"(lp) : "f"(l1), "f"(l0));
                yf[mt][0][kt][r] = hp;
                yf[mt][1][kt][r] = lp;
            }

    // ----- lm-head mma passes + in-register online LSE -----
    float m_r[4] = {-1e30f, -1e30f, -1e30f, -1e30f};
    float s_r[4] = {0.f, 0.f, 0.f, 0.f};
    float acc[2][5][4];

#define MMA_PASS(NTS, CNT)                                                     \
    {                                                                          \
        _Pragma("unroll")                                                      \
        for (int nn = 0; nn < (CNT); nn++) {                                   \
            int v0 = ((NTS) + nn) * 8 + tig * 2;                               \
            float b0 = s_bias[v0], b1 = s_bias[v0 + 1];                        \
            _Pragma("unroll")                                                  \
            for (int mt = 0; mt < 2; mt++) {                                   \
                acc[mt][nn][0] = b0; acc[mt][nn][1] = b1;                      \
                acc[mt][nn][2] = b0; acc[mt][nn][3] = b1;                      \
            }                                                                  \
        }                                                                      \
        _Pragma("unroll")                                                      \
        for (int nn = 0; nn < (CNT); nn++) {                                   \
            int nt = (NTS) + nn;                                               \
            uint4 bh = *reinterpret_cast<const uint4*>(s_bf + (nt * 2 + 0) * 128 + lane * 4); \
            uint4 bl = *reinterpret_cast<const uint4*>(s_bf + (nt * 2 + 1) * 128 + lane * 4); \
            _Pragma("unroll")                                                  \
            for (int mt = 0; mt < 2; mt++) {                                   \
                mma_bf16(acc[mt][nn], yf[mt][0][0], bh.x, bh.y);               \
                mma_bf16(acc[mt][nn], yf[mt][0][1], bh.z, bh.w);               \
                mma_bf16(acc[mt][nn], yf[mt][1][0], bh.x, bh.y);               \
                mma_bf16(acc[mt][nn], yf[mt][1][1], bh.z, bh.w);               \
                mma_bf16(acc[mt][nn], yf[mt][0][0], bl.x, bl.y);               \
                mma_bf16(acc[mt][nn], yf[mt][0][1], bl.z, bl.w);               \
            }                                                                  \
        }                                                                      \
        _Pragma("unroll")                                                      \
        for (int nn = 0; nn < (CNT); nn++) {                                   \
            int v0 = ((NTS) + nn) * 8 + tig * 2;                               \
            _Pragma("unroll")                                                  \
            for (int mt = 0; mt < 2; mt++) {                                   \
                int r0 = wbase + mt * 16 + gid;                                \
                if (v0 < 65) {                                                 \
                    s_un[r0 * 65 + v0]       = acc[mt][nn][0];                 \
                    s_un[(r0 + 8) * 65 + v0] = acc[mt][nn][2];                 \
                }                                                              \
                if (v0 + 1 < 65) {                                             \
                    s_un[r0 * 65 + v0 + 1]       = acc[mt][nn][1];             \
                    s_un[(r0 + 8) * 65 + v0 + 1] = acc[mt][nn][3];             \
                }                                                              \
            }                                                                  \
        }                                                                      \
        _Pragma("unroll")                                                      \
        for (int q = 0; q < 4; q++) {                                          \
            int mt = q >> 1, hh = (q & 1) * 2;                                 \
            float l[2 * (CNT)];                                                \
            float cm = -1e30f;                                                 \
            _Pragma("unroll")                                                  \
            for (int nn = 0; nn < (CNT); nn++) {                               \
                int v0 = ((NTS) + nn) * 8 + tig * 2;                           \
                l[2 * nn]     = (v0 < 65)     ? acc[mt][nn][hh]     : -1e30f;  \
                l[2 * nn + 1] = (v0 + 1 < 65) ? acc[mt][nn][hh + 1] : -1e30f;  \
                cm = fmaxf(cm, fmaxf(l[2 * nn], l[2 * nn + 1]));               \
            }                                                                  \
            float mn = fmaxf(m_r[q], cm);                                      \
            float s2 = s_r[q] * __expf(m_r[q] - mn);                           \
            _Pragma("unroll")                                                  \
            for (int j = 0; j < 2 * (CNT); j++) s2 += __expf(l[j] - mn);       \
            m_r[q] = mn; s_r[q] = s2;                                          \
        }                                                                      \
    }
    MMA_PASS(0, 5)
    MMA_PASS(5, 4)
#undef MMA_PASS

    // ----- combine LSE partials across the 4 tig lanes (bfly) -----
#pragma unroll
    for (int mask = 1; mask <= 2; mask <<= 1) {
#pragma unroll
        for (int q = 0; q < 4; q++) {
            float mo = __shfl_xor_sync(0xffffffffu, m_r[q], mask);
            float so = __shfl_xor_sync(0xffffffffu, s_r[q], mask);
            float mn = fmaxf(m_r[q], mo);
            s_r[q] = s_r[q] * __expf(m_r[q] - mn) + so * __expf(mo - mn);
            m_r[q] = mn;
        }
    }
    __syncthreads();   // stage complete for ltgt reads + flush

    // lane reports row = wbase + tig*8 + gid  (q = tig)
    float msel = m_r[0], ssel = s_r[0];
    if (tig == 1) { msel = m_r[1]; ssel = s_r[1]; }
    else if (tig == 2) { msel = m_r[2]; ssel = s_r[2]; }
    else if (tig == 3) { msel = m_r[3]; ssel = s_r[3]; }
    int trow = wbase + tig * 8 + gid;
    float ltgt = s_un[trow * 65 + s_tgt[trow]];
    float lossi = (msel + __logf(ssel)) - ltgt;

    // warp then block reduce; last block writes mean
#pragma unroll
    for (int off = 16; off > 0; off >>= 1)
        lossi += __shfl_down_sync(0xffffffffu, lossi, off);
    if ((tid & 31) == 0) s_lred[tid >> 5] = lossi;
    __syncthreads();
    if (tid == 0) {
        atomicAdd(&g_loss, s_lred[0] + s_lred[1] + s_lred[2] + s_lred[3]);
        __threadfence();
        unsigned prev = atomicAdd(&g_done, 1u);
        if ((int)prev == nblocks - 1 && loss_idx >= 0)
            out[loss_idx] = g_loss * inv_n;
    }

    // ----- single TMA bulk store: stage -> GMEM logits -----
    if (write_logits && tid == 0) {
        u32 saddr;
        asm("{ .reg .u64 tmp; cvta.to.shared.u64 tmp, %1; cvt.u32.u64 %0, tmp; }"
            : "=r"(saddr) : "l"(s_un));
        const float* gdst = out + (size_t)blockIdx.x * 8320;
        asm volatile("fence.proxy.async.shared::cta;" ::: "memory");
        asm volatile("cp.async.bulk.global.shared::cta.bulk_group [%0], [%1], %2;"
                     :: "l"(gdst), "r"(saddr), "r"(33280) : "memory");
        asm volatile("cp.async.bulk.commit_group;" ::: "memory");
        asm volatile("cp.async.bulk.wait_group.read 0;" ::: "memory");
    }
}

extern "C" void kernel_launch(void* const* d_in, const int* in_sizes, int n_in,
                              void* d_out, int out_size) {
    const int*   idx     = (const int*)d_in[0];
    const int*   targets = (const int*)d_in[1];
    const float* tok_emb = (const float*)d_in[2];
    const float* pos_emb = (const float*)d_in[3];
    const float* Wq      = (const float*)d_in[4];
    const float* Wk      = (const float*)d_in[5];
    const float* Wv      = (const float*)d_in[6];
    const float* Wmlp    = (const float*)d_in[7];
    const float* bmlp    = (const float*)d_in[8];
    const float* Wlm     = (const float*)d_in[9];
    const float* blm     = (const float*)d_in[10];
    float* out = (float*)d_out;

    const long nrows = in_sizes[0];           // B*T = 524288
    const long total = nrows * VOCAB;
    int write_logits = ((long)out_size >= total) ? 1 : 0;
    int loss_idx = -1;
    if ((long)out_size == total + 1) loss_idx = (int)total;
    else if (out_size == 1)          { loss_idx = 0; write_logits = 0; }

    int work = 520 * 32 + PACK_N + 2304 + 1024;
    k_tables<<<(work + 255) / 256, 256>>>(tok_emb, pos_emb, Wq, Wk, Wv,
                                          Wmlp, bmlp, Wlm, blm);
    {
        void* src = nullptr;
        cudaGetSymbolAddress(&src, g_pack);
        cudaMemcpyToSymbolAsync(c_all, src, PACK_N * sizeof(float), 0,
                                cudaMemcpyDeviceToDevice);
    }

    int nblocks = (int)(nrows / 128);
    k_main<<<nblocks, 128>>>(idx, targets, out, write_logits, loss_idx,
                             1.0f / (float)nrows, nblocks);
}